// round 16
// baseline (speedup 1.0000x reference)
#include <cuda_runtime.h>
#include <cuda_fp16.h>
#include <math.h>

// ---------------------------------------------------------------------------
// AliasFreeConv: modulated 3x3 conv (demod) + 2x up (12-tap) + lrelu + 2x down
// R16: split-K conv (2048 CTAs x 36 iters -> g_A0/g_A1, tail 13.5%->1%),
// demod+bias folded into filter load, g_xh zeroing dropped (static zero-init),
// launches merged to 4: pre1, pre2, conv(#3), filter(#4).
// ---------------------------------------------------------------------------

#define BATCH 8
#define CIN   512
#define COUT  512
#define HW    64
#define HC    62
#define HU    128
#define NTAPS 12
#define XP    68              // padded spatial for channels-last input

#define LIN_SCALE 0.044194173824159216f   // 1/sqrt(512)
#define WSCALE    0.014731391274719742f   // 1/sqrt(512*9)
#define WSCALE2   2.170138888888889e-4f   // 1/4608
#define EPSV      1e-8f
#define NEG_SLOPE 0.2f
#define LRELU_SC  1.4142135623730951f

#define XT_ELEMS (BATCH*XP*XP*512)        // 18,939,904 fp16
#define WT_ELEMS (9*512*512)              // 2,359,296 fp16

// ------------------------- scratch (device globals) ------------------------
// NOTE: device globals are zero-initialized at module load; prep_x only writes
// the valid region, so g_xh padding stays zero on every replay.
__device__ float g_s  [BATCH*CIN];
__device__ float g_g  [BATCH*COUT];
__device__ float g_wsq[COUT*CIN];
__device__ float g_A0 [BATCH*COUT*HC*HC];          // conv partial (chunks 0-3)
__device__ float g_A1 [BATCH*COUT*HC*HC];          // conv partial (chunks 4-7)
__device__ __align__(16) __half g_xh [XT_ELEMS];   // fp16(x*wscale*s)
__device__ __align__(16) __half g_wh [WT_ELEMS];   // [tap][co][ci] fp16

// ------------------------- PTX helpers -------------------------------------
__device__ __forceinline__ unsigned smem_u32(const void* p) {
    unsigned a;
    asm("{ .reg .u64 t; cvta.to.shared.u64 t, %1; cvt.u32.u64 %0, t; }"
        : "=r"(a) : "l"(p));
    return a;
}
__device__ __forceinline__ void cp16(unsigned dst, const void* src) {
    asm volatile("cp.async.cg.shared.global [%0], [%1], 16;"
                 :: "r"(dst), "l"(src) : "memory");
}
__device__ __forceinline__ void cp_commit() {
    asm volatile("cp.async.commit_group;" ::: "memory");
}
__device__ __forceinline__ void cp_wait0() {
    asm volatile("cp.async.wait_group 0;" ::: "memory");
}
#define MMA16816(d, a0, a1, a2, a3, b0, b1) \
    asm volatile("mma.sync.aligned.m16n8k16.row.col.f32.f16.f16.f32 " \
        "{%0,%1,%2,%3}, {%4,%5,%6,%7}, {%8,%9}, {%0,%1,%2,%3};" \
        : "+f"((d)[0]), "+f"((d)[1]), "+f"((d)[2]), "+f"((d)[3]) \
        : "r"(a0), "r"(a1), "r"(a2), "r"(a3), "r"(b0), "r"(b1))
#define LDSM4(r0, r1, r2, r3, addr) \
    asm volatile("ldmatrix.sync.aligned.m8n8.x4.shared.b16 {%0,%1,%2,%3}, [%4];" \
        : "=r"(r0), "=r"(r1), "=r"(r2), "=r"(r3) : "r"(addr))

// ------------------------- L1: style + wsq ---------------------------------
__global__ __launch_bounds__(256)
void k_pre1(const float* __restrict__ style, const float* __restrict__ mod_w,
            const float* __restrict__ mod_b, const float* __restrict__ cw) {
    int bid = blockIdx.x;
    int tid = threadIdx.x;
    if (bid < 512) {
        int w    = bid * 8 + (tid >> 5);
        int lane = tid & 31;
        int b = w >> 9, c = w & 511;
        const float* sp = style + b * 512;
        const float* mp = mod_w + c * 512;
        float sum = 0.f;
        #pragma unroll 4
        for (int d = lane; d < 512; d += 32) sum += sp[d] * mp[d];
        #pragma unroll
        for (int off = 16; off; off >>= 1)
            sum += __shfl_xor_sync(0xffffffffu, sum, off);
        if (lane == 0) g_s[w] = sum * LIN_SCALE + mod_b[c];
    } else {
        int i = (bid - 512) * 256 + tid;
        if (i < COUT * CIN) {
            float s = 0.f;
            #pragma unroll
            for (int k = 0; k < 9; k++) { float v = cw[i * 9 + k]; s += v * v; }
            g_wsq[i] = s;
        }
    }
}

// ------------------------- L2: demod + prep_w + prep_x ---------------------
__global__ __launch_bounds__(256)
void k_pre2(const float* __restrict__ cw, const float* __restrict__ x) {
    __shared__ float t[32][33];
    int bid = blockIdx.x;
    int tid = threadIdx.x;
    if (bid < 512) {
        // demod: g = rsqrt(wscale^2 * sum s^2*wsq + eps)/(1+eps)
        int w    = bid * 8 + (tid >> 5);
        int lane = tid & 31;
        int b = w >> 9, co = w & 511;
        const float* sp = g_s   + b  * 512;
        const float* wq = g_wsq + co * 512;
        float sum = 0.f;
        #pragma unroll 4
        for (int d = lane; d < 512; d += 32) {
            float sv = sp[d]; sum += sv * sv * wq[d];
        }
        #pragma unroll
        for (int off = 16; off; off >>= 1)
            sum += __shfl_xor_sync(0xffffffffu, sum, off);
        if (lane == 0) g_g[w] = 1.0f / ((1.0f + EPSV) * sqrtf(WSCALE2 * sum + EPSV));
    } else if (bid < 512 + 9216) {
        // weights -> [tap][co][ci] fp16
        int i = (bid - 512) * 256 + tid;
        if (i < WT_ELEMS) {
            int ci  = i & 511;
            int co  = (i >> 9) & 511;
            int tap = i >> 18;
            g_wh[i] = __float2half_rn(cw[(co * 512 + ci) * 9 + tap]);
        }
    } else {
        // x -> channels-last fp16 (valid region only; padding stays zero)
        int pid  = bid - (512 + 9216);         // [0, 16384)
        int xt   = pid & 1;
        int ci_t = (pid >> 1) & 15;
        int y    = (pid >> 5) & 63;
        int b    = pid >> 11;
        int tx = tid & 31, ty = tid >> 5;      // (32, 8)

        #pragma unroll
        for (int j = 0; j < 4; j++) {
            int ci = ci_t * 32 + ty + 8 * j;
            int xx = xt * 32 + tx;
            float v = x[((((b << 9) + ci) << 6) + y) * 64 + xx];
            t[ty + 8 * j][tx] = v * (WSCALE * g_s[(b << 9) + ci]);
        }
        __syncthreads();
        #pragma unroll
        for (int j = 0; j < 4; j++) {
            int xx = xt * 32 + ty + 8 * j;
            int ci = ci_t * 32 + tx;
            long o = ((long)(b * XP + y) * XP + xx) * 512 + ci;
            g_xh[o] = __float2half_rn(t[tx][ty + 8 * j]);
        }
    }
}

// ------------------------- L3: mma.sync conv (fp16, split-K) ---------------
// CTA tile: M=128 co x N=128 pixels (8y x 16x), split-K over ci: half h does
// chunks h*4..h*4+3 (36 K=64 iters in 18 pairs) -> raw sums to g_A{0,1}.
// 8 warps = 2(m) x 4(n), warp tile 64x32, mma m16n8k16. W 4-buffered
// (prefetch distance 2), X double-buffered in 8 slices/window with parity
// shift (no pair writes a buffer another compute in that pair reads).
// Smem XOR-swizzled 128B rows: X 2x23040 @0, W 4x16384 @46080 -> 111616 B.
#define OFF_WS    46080u
#define WS_BYTES  16384u
#define XS_BYTES  23040u
#define SMEM_CONV 111616

__global__ __launch_bounds__(256, 2)
void k_conv_mma() {
    extern __shared__ __align__(16) char smc[];
    unsigned sbase = smem_u32(smc);

    int tid  = threadIdx.x;
    int wid  = tid >> 5, lane = tid & 31;
    int g    = lane >> 2, t4 = lane & 3;
    int wm   = wid >> 2;                      // 0..1 -> co offset wm*64
    int wn   = wid & 3;                       // 0..3 -> pixel offset wn*32

    int bidx = blockIdx.x;          // 2048 = b(8)*coT(4)*half(2)*yT(8)*xT(4)
    int xT   = bidx & 3;
    int yT   = (bidx >> 2) & 7;
    int half = (bidx >> 5) & 1;
    int coT  = (bidx >> 6) & 3;
    int b    = bidx >> 8;
    int co0  = coT << 7;
    int y0   = yT << 3;
    int x0   = xT << 4;
    int ch0  = half << 2;                     // first ci chunk

    const __half* xB = g_xh + (long)b * XP * XP * 512;

    float acc[4][4][4];
    #pragma unroll
    for (int mi = 0; mi < 4; mi++)
        #pragma unroll
        for (int ni = 0; ni < 4; ni++)
            #pragma unroll
            for (int q = 0; q < 4; q++) acc[mi][ni][q] = 0.f;

    auto stageW = [&](int it) {               // it in [0,36)
        int kwl = it / 9, tap = it - kwl * 9;
        const __half* wp = g_wh + ((long)tap << 18) + (long)co0 * 512
                           + ((ch0 + kwl) << 6);
        unsigned dst = sbase + OFF_WS + (unsigned)(it & 3) * WS_BYTES;
        #pragma unroll
        for (int k = 0; k < 4; k++) {                 // 1024 x 16B
            int c = tid + (k << 8);
            int row = c >> 3, cc = c & 7;
            cp16(dst + (unsigned)(row << 7) + (unsigned)(((cc ^ (row & 7)) << 4)),
                 wp + row * 512 + (cc << 3));
        }
    };
    auto stageXslice = [&](int kwl, int s) {  // local window 0..3, slice 0..7
        const __half* xp = xB + ((ch0 + kwl) << 6);
        unsigned dst = sbase + (unsigned)(kwl & 1) * XS_BYTES;
        int c = s * 180 + tid;
        if (tid < 180) {
            int row = c >> 3, cc = c & 7;
            int gy = y0 + row / 18, gx = x0 + row % 18;
            cp16(dst + (unsigned)(row << 7) + (unsigned)((cc ^ (row & 7)) << 4),
                 xp + (long)(gy * XP + gx) * 512 + (cc << 3));
        }
    };
    auto stageXfull = [&](int kwl) {
        const __half* xp = xB + ((ch0 + kwl) << 6);
        unsigned dst = sbase + (unsigned)(kwl & 1) * XS_BYTES;
        for (int c = tid; c < 1440; c += 256) {
            int row = c >> 3, cc = c & 7;
            int gy = y0 + row / 18, gx = x0 + row % 18;
            cp16(dst + (unsigned)(row << 7) + (unsigned)((cc ^ (row & 7)) << 4),
                 xp + (long)(gy * XP + gx) * 512 + (cc << 3));
        }
    };

    // per-lane fragment constants
    int r7  = lane & 7;
    int cA  = lane >> 4;
    unsigned rowByteA = (unsigned)((wm * 64 + (lane & 15)) << 7);
    int pxc = (((lane >> 4) & 1) << 3) + (lane & 7);
    int cB  = (lane >> 3) & 1;

    auto compute = [&](int i) {
        int kwl = i / 9, tap = i - kwl * 9;
        int ky = tap / 3, kx = tap - 3 * (tap / 3);
        unsigned wsB = sbase + OFF_WS + (unsigned)(i & 3) * WS_BYTES + rowByteA;
        unsigned xO  = sbase + (unsigned)(kwl & 1) * XS_BYTES;
        int rowB0 = (wn * 2 + ky) * 18 + pxc + kx;
        int rowB1 = rowB0 + 18;
        unsigned b0 = xO + (unsigned)(rowB0 << 7);
        unsigned b1 = xO + (unsigned)(rowB1 << 7);
        int s0 = rowB0 & 7, s1 = rowB1 & 7;

        #pragma unroll
        for (int kb = 0; kb < 4; kb++) {
            unsigned bq0, bq1, bq2, bq3, bq4, bq5, bq6, bq7;
            LDSM4(bq0, bq1, bq2, bq3, b0 + (unsigned)(((cB + 2 * kb) ^ s0) << 4));
            LDSM4(bq4, bq5, bq6, bq7, b1 + (unsigned)(((cB + 2 * kb) ^ s1) << 4));
            unsigned offA = (unsigned)(((cA + 2 * kb) ^ r7) << 4);
            #pragma unroll
            for (int mi = 0; mi < 4; mi++) {
                unsigned a0, a1, a2, a3;
                LDSM4(a0, a1, a2, a3, wsB + (unsigned)(mi * 2048) + offA);
                MMA16816(acc[mi][0], a0, a1, a2, a3, bq0, bq1);
                MMA16816(acc[mi][1], a0, a1, a2, a3, bq2, bq3);
                MMA16816(acc[mi][2], a0, a1, a2, a3, bq4, bq5);
                MMA16816(acc[mi][3], a0, a1, a2, a3, bq6, bq7);
            }
        }
    };

    // prologue: X local window 0 + W(0), W(1)
    stageXfull(0);
    stageW(0); stageW(1);
    cp_commit();
    cp_wait0();
    __syncthreads();

    #pragma unroll 1
    for (int pp = 0; pp < 18; pp++) {
        int i0 = pp << 1, i1 = i0 + 1;
        if (i0 + 2 < 36) stageW(i0 + 2);
        if (i1 + 2 < 36) stageW(i1 + 2);
        // X slices: local window kwl+1, slice (pos - (kwl&1)) when in [0,8)
        #pragma unroll
        for (int u = 0; u < 2; u++) {
            int i  = i0 + u;
            int kw = i / 9, ps = i - kw * 9;
            int sl = ps - (kw & 1);
            if (kw < 3 && sl >= 0 && sl < 8) stageXslice(kw + 1, sl);
        }
        cp_commit();

        compute(i0);
        compute(i1);

        cp_wait0();
        __syncthreads();
    }

    // epilogue: raw partial sums -> g_A0 / g_A1 (demod+bias applied in filter)
    float* gA = half ? g_A1 : g_A0;
    #pragma unroll
    for (int mi = 0; mi < 4; mi++) {
        int coL = co0 + wm * 64 + mi * 16 + g;
        int coH = coL + 8;
        float* apL = gA + (long)((b << 9) + coL) * (HC * HC);
        float* apH = gA + (long)((b << 9) + coH) * (HC * HC);
        #pragma unroll
        for (int ni = 0; ni < 4; ni++) {
            int p0 = wn * 32 + ni * 8;
            int py = p0 >> 4, px = (p0 & 15) + 2 * t4;
            int oy = y0 + py, ox = x0 + px;
            if (oy < HC) {
                if (ox < HC) {
                    apL[oy * HC + ox] = acc[mi][ni][0];
                    apH[oy * HC + ox] = acc[mi][ni][2];
                }
                if (ox + 1 < HC) {
                    apL[oy * HC + ox + 1] = acc[mi][ni][1];
                    apH[oy * HC + ox + 1] = acc[mi][ni][3];
                }
            }
        }
    }
}

// ------------------------- L4: fused filter chain (coarsened) --------------
// 2 blocks per (b,co) plane: output rows [0,32) / [32,64).
//   half0: A rows [0,36),  C rows [0,69)   half1: A rows [25,62), C rows [58,128)
// Load phase combines split-K partials: sA = (A0+A1)*demod + bias.
// smem floats: sA@0 (2520), sB@2520 (5160), sC@7680 (70*130=9100),
//              sD@0 (70*65=4550, reuses sA/sB), kfu@16780, kfd@16792 -> 67216B
#define SMEM_FILT3 (16804 * 4)

__global__ __launch_bounds__(256)
void k_filter(const float* __restrict__ uf, const float* __restrict__ df,
              const float* __restrict__ act_b, float* __restrict__ out) {
    extern __shared__ float sm[];
    float* sA  = sm;
    float* sB  = sm + 2520;
    float* sC  = sm + 7680;
    float* sD  = sm;                 // reuse (sA/sB dead by phase 3)
    float* kfu = sm + 16780;
    float* kfd = sm + 16792;

    int bid  = blockIdx.x;
    int half = bid & 1;
    int p    = bid >> 1;
    int tid  = threadIdx.x;

    int r0 = half ? 25 : 0;          // first A row staged
    int NR = half ? 37 : 36;         // A rows staged
    int j0 = half ? 58 : 0;          // first C row produced (even)
    int NJ = half ? 70 : 69;         // C rows produced
    int m0 = half << 5;              // first output row

    if (tid < NTAPS)          kfu[tid] = uf[tid] * 2.0f;
    else if (tid < 2 * NTAPS) kfd[tid - NTAPS] = df[tid - NTAPS];

    // phase 0: load A rows [r0, r0+NR): combine partials, demod, bias
    const float* A0p = g_A0 + (long)p * (HC * HC);
    const float* A1p = g_A1 + (long)p * (HC * HC);
    float gg = g_g[p];
    float bb = act_b[p & 511];
    for (int i = tid; i < NR * HC; i += 256) {
        int r = i / HC, c = i - r * HC;
        int idx = (r0 + r) * HC + c;
        sA[r * 63 + c] = (A0p[idx] + A1p[idx]) * gg + bb;
    }
    __syncthreads();

    // phase 1: up-x -> sB[NR][128]. 8 outputs per task from 10 loads.
    for (int i = tid; i < NR * 16; i += 256) {
        int t = i & 15, lr = i >> 4;
        int n0 = t << 3;
        int base = (n0 >> 1) - 4;
        const float* row = sA + lr * 63;
        float r[10];
        #pragma unroll
        for (int kk = 0; kk < 10; kk++) {
            int j = base + kk;
            r[kk] = ((unsigned)j < 62u) ? row[j] : 0.f;
        }
        float* orow = sB + lr * 129 + n0;
        #pragma unroll
        for (int d = 0; d < 8; d++) {
            const int s0 = (d + 3) & 1;
            float acc = 0.f;
            #pragma unroll
            for (int q = 0; q < 6; q++) {
                const int s  = s0 + 2 * q;
                const int kk = ((d + 3 - s) >> 1) + 4;   // compile-time
                acc += kfu[s] * r[kk];
            }
            orow[d] = acc;
        }
    }
    __syncthreads();

    // phase 2: up-y + lrelu -> sC rows [j0, j0+NJ). j0 even => taps fold.
    for (int i = tid; i < 9 * 128; i += 256) {
        int xcol = i & 127, gidx = i >> 7;
        int mg = j0 + (gidx << 3);
        int base = (mg >> 1) - 4;             // global A-row idx base
        float r[10];
        #pragma unroll
        for (int kk = 0; kk < 10; kk++) {
            int lr = base + kk - r0;
            r[kk] = ((unsigned)lr < (unsigned)NR) ? sB[lr * 129 + xcol] : 0.f;
        }
        #pragma unroll
        for (int d = 0; d < 8; d++) {
            const int s0 = (d + 3) & 1;
            float acc = 0.f;
            #pragma unroll
            for (int q = 0; q < 6; q++) {
                const int s  = s0 + 2 * q;
                const int kk = ((d + 3 - s) >> 1) + 4;
                acc += kfu[s] * r[kk];
            }
            acc = (acc >= 0.f ? acc : NEG_SLOPE * acc) * LRELU_SC;
            int lj = (gidx << 3) + d;
            if (lj < NJ) sC[lj * 130 + xcol] = acc;
        }
    }
    // zero-fill float2 pair 64 (elements 128,129) of each sC row
    for (int i = tid; i < 70; i += 256) {
        sC[i * 130 + 128] = 0.f;
        sC[i * 130 + 129] = 0.f;
    }
    __syncthreads();

    // phase 3: down-x -> sD[NJ][64]. 2 outputs per task from 8 LDS.64.
    for (int i = tid; i < NJ * 32; i += 256) {
        int t = i & 31, lj = i >> 5;
        int n0 = t << 1;
        const float2* row2 = (const float2*)(sC + lj * 130);
        float2 r2[8];
        #pragma unroll
        for (int kk = 0; kk < 8; kk++) {
            int pi = n0 - 3 + kk;
            r2[kk] = ((unsigned)pi < 65u) ? row2[pi] : make_float2(0.f, 0.f);
        }
        float a0 = 0.f, a1 = 0.f;
        #pragma unroll
        for (int kk = 0; kk < 8; kk++) {
            const int sx0 = 12 - 2 * kk, sy0 = 11 - 2 * kk;   // out n0
            const int sx1 = 14 - 2 * kk, sy1 = 13 - 2 * kk;   // out n0+1
            if (sx0 >= 0 && sx0 <= 11) a0 += kfd[sx0] * r2[kk].x;
            if (sy0 >= 0 && sy0 <= 11) a0 += kfd[sy0] * r2[kk].y;
            if (sx1 >= 0 && sx1 <= 11) a1 += kfd[sx1] * r2[kk].x;
            if (sy1 >= 0 && sy1 <= 11) a1 += kfd[sy1] * r2[kk].y;
        }
        sD[lj * 65 + n0]     = a0;
        sD[lj * 65 + n0 + 1] = a1;
    }
    __syncthreads();

    // phase 4: down-y -> out rows [m0, m0+32). 4 outputs per task, 18 loads.
    float* op = out + (long)p * 4096;
    for (int i = tid; i < 512; i += 256) {
        int xcol = i & 63, u = i >> 6;
        int mg = m0 + (u << 2);
        float r[18];
        #pragma unroll
        for (int kk = 0; kk < 18; kk++) {
            int j  = 2 * mg - 5 + kk;
            int lr = j - j0;
            r[kk] = ((unsigned)j < 128u && (unsigned)lr < (unsigned)NJ)
                        ? sD[lr * 65 + xcol] : 0.f;
        }
        #pragma unroll
        for (int d = 0; d < 4; d++) {
            float acc = 0.f;
            #pragma unroll
            for (int kk = 0; kk < 18; kk++) {
                const int s = 2 * d + 11 - kk;
                if (s >= 0 && s <= 11) acc += kfd[s] * r[kk];
            }
            op[(mg + d) * 64 + xcol] = acc;
        }
    }
}

// ---------------------------------------------------------------------------
extern "C" void kernel_launch(void* const* d_in, const int* in_sizes, int n_in,
                              void* d_out, int out_size) {
    const float* x      = (const float*)d_in[0];
    const float* style  = (const float*)d_in[1];
    const float* mod_w  = (const float*)d_in[2];
    const float* mod_b  = (const float*)d_in[3];
    const float* conv_w = (const float*)d_in[4];
    const float* act_b  = (const float*)d_in[5];
    const float* up_f   = (const float*)d_in[6];
    const float* down_f = (const float*)d_in[7];
    float* out = (float*)d_out;

    cudaFuncSetAttribute(k_filter, cudaFuncAttributeMaxDynamicSharedMemorySize,
                         SMEM_FILT3);
    cudaFuncSetAttribute(k_conv_mma, cudaFuncAttributeMaxDynamicSharedMemorySize,
                         SMEM_CONV);

    k_pre1<<<1536, 256>>>(style, mod_w, mod_b, conv_w);            // #1
    k_pre2<<<512 + 9216 + 16384, 256>>>(conv_w, x);                // #2
    k_conv_mma<<<2048, 256, SMEM_CONV>>>();                        // #3
    k_filter<<<BATCH * COUT * 2, 256, SMEM_FILT3>>>(up_f, down_f, act_b, out); // #4
}